// round 1
// baseline (speedup 1.0000x reference)
#include <cuda_runtime.h>

// Pairwise squared Euclidean distance:
//   dist[i,j] = ||s_i||^2 + ||t_j||^2 - 2 * <s_i, t_j>
// s: [n, 64] fp32, t: [q, 64] fp32, out: [n, q] fp32 (row-major).
// n = q = 16384, d = 64 for this problem.

#define D   64
#define BM  128
#define BN  128
#define BK  32
#define TM  8
#define TN  8
#define LDA (BM + 4)   // padded smem stride (floats); 132*4B = 528B, 16B-aligned

#define MAXNQ 16384

__device__ float g_s_sq[MAXNQ];
__device__ float g_t_sq[MAXNQ];

// Row squared-norms. grid.y == 0 -> s, grid.y == 1 -> t.
__global__ void norms_kernel(const float* __restrict__ s,
                             const float* __restrict__ t,
                             int n, int q) {
    int i = blockIdx.x * blockDim.x + threadIdx.x;
    if (blockIdx.y == 0) {
        if (i < n) {
            const float4* row = reinterpret_cast<const float4*>(s + (size_t)i * D);
            float acc = 0.f;
#pragma unroll
            for (int j = 0; j < D / 4; j++) {
                float4 v = row[j];
                acc += v.x * v.x + v.y * v.y + v.z * v.z + v.w * v.w;
            }
            g_s_sq[i] = acc;
        }
    } else {
        if (i < q) {
            const float4* row = reinterpret_cast<const float4*>(t + (size_t)i * D);
            float acc = 0.f;
#pragma unroll
            for (int j = 0; j < D / 4; j++) {
                float4 v = row[j];
                acc += v.x * v.x + v.y * v.y + v.z * v.z + v.w * v.w;
            }
            g_t_sq[i] = acc;
        }
    }
}

// 128x128 output tile per CTA, 256 threads, 8x8 per thread.
// Smem tiles stored K-major (transposed) with +4 padding so the transposed
// scalar stores are conflict-free and the compute-side LDS.128 stay aligned.
__global__ __launch_bounds__(256, 2)
void dist_kernel(const float* __restrict__ s,
                 const float* __restrict__ t,
                 float* __restrict__ out,
                 int n, int q) {
    __shared__ float sA[BK * LDA];
    __shared__ float sB[BK * LDA];

    const int tid = threadIdx.x;
    const int tx  = tid & 15;   // 0..15 -> column micro-tile
    const int ty  = tid >> 4;   // 0..15 -> row micro-tile

    const int rowBase = blockIdx.y * BM;  // into s / output rows
    const int colBase = blockIdx.x * BN;  // into t / output cols

    float acc[TM][TN];
#pragma unroll
    for (int i = 0; i < TM; i++)
#pragma unroll
        for (int j = 0; j < TN; j++) acc[i][j] = 0.f;

    // Loader mapping: 256 threads, each loads 4 float4 per tile per chunk.
    const int tRow = tid >> 3;        // 0..31
    const int tCol = (tid & 7) * 4;   // 0,4,...,28 (k offset within chunk)

    for (int kb = 0; kb < D; kb += BK) {
#pragma unroll
        for (int r = 0; r < 4; r++) {
            const int row = r * 32 + tRow;  // 0..127
            const float4 va = *reinterpret_cast<const float4*>(
                s + (size_t)(rowBase + row) * D + kb + tCol);
            const float4 vb = *reinterpret_cast<const float4*>(
                t + (size_t)(colBase + row) * D + kb + tCol);
            sA[(tCol + 0) * LDA + row] = va.x;
            sA[(tCol + 1) * LDA + row] = va.y;
            sA[(tCol + 2) * LDA + row] = va.z;
            sA[(tCol + 3) * LDA + row] = va.w;
            sB[(tCol + 0) * LDA + row] = vb.x;
            sB[(tCol + 1) * LDA + row] = vb.y;
            sB[(tCol + 2) * LDA + row] = vb.z;
            sB[(tCol + 3) * LDA + row] = vb.w;
        }
        __syncthreads();

#pragma unroll 8
        for (int k = 0; k < BK; k++) {
            float a[TM], b[TN];
            *reinterpret_cast<float4*>(&a[0]) =
                *reinterpret_cast<const float4*>(&sA[k * LDA + ty * TM]);
            *reinterpret_cast<float4*>(&a[4]) =
                *reinterpret_cast<const float4*>(&sA[k * LDA + ty * TM + 4]);
            *reinterpret_cast<float4*>(&b[0]) =
                *reinterpret_cast<const float4*>(&sB[k * LDA + tx * TN]);
            *reinterpret_cast<float4*>(&b[4]) =
                *reinterpret_cast<const float4*>(&sB[k * LDA + tx * TN + 4]);
#pragma unroll
            for (int i = 0; i < TM; i++)
#pragma unroll
                for (int j = 0; j < TN; j++)
                    acc[i][j] = fmaf(a[i], b[j], acc[i][j]);
        }
        __syncthreads();
    }

    // Epilogue: dist = s_sq + t_sq - 2*cross, vectorized stores.
    float ssq[TM], tsq[TN];
#pragma unroll
    for (int i = 0; i < TM; i++) ssq[i] = g_s_sq[rowBase + ty * TM + i];
#pragma unroll
    for (int j = 0; j < TN; j++) tsq[j] = g_t_sq[colBase + tx * TN + j];

#pragma unroll
    for (int i = 0; i < TM; i++) {
        const size_t o = (size_t)(rowBase + ty * TM + i) * q + colBase + tx * TN;
        float4 v0, v1;
        v0.x = ssq[i] + tsq[0] - 2.f * acc[i][0];
        v0.y = ssq[i] + tsq[1] - 2.f * acc[i][1];
        v0.z = ssq[i] + tsq[2] - 2.f * acc[i][2];
        v0.w = ssq[i] + tsq[3] - 2.f * acc[i][3];
        v1.x = ssq[i] + tsq[4] - 2.f * acc[i][4];
        v1.y = ssq[i] + tsq[5] - 2.f * acc[i][5];
        v1.z = ssq[i] + tsq[6] - 2.f * acc[i][6];
        v1.w = ssq[i] + tsq[7] - 2.f * acc[i][7];
        *reinterpret_cast<float4*>(out + o)     = v0;
        *reinterpret_cast<float4*>(out + o + 4) = v1;
    }
}

extern "C" void kernel_launch(void* const* d_in, const int* in_sizes, int n_in,
                              void* d_out, int out_size) {
    const float* s = (const float*)d_in[0];
    const float* t = (const float*)d_in[1];
    float* out = (float*)d_out;

    const int n = in_sizes[0] / D;
    const int q = in_sizes[1] / D;

    const int mx = (n > q ? n : q);
    dim3 ngrid((mx + 255) / 256, 2);
    norms_kernel<<<ngrid, 256>>>(s, t, n, q);

    dim3 grid(q / BN, n / BM);
    dist_kernel<<<grid, 256>>>(s, t, out, n, q);
}

// round 2
// speedup vs baseline: 2.5290x; 2.5290x over previous
#include <cuda_runtime.h>
#include <cstdint>

// dist[i,j] = ||s_i||^2 + ||t_j||^2 - 2 <s_i, t_j>
// s: [n, 64] fp32, t: [q, 64] fp32, out: [n, q] fp32. n = q = 16384.
// Cross term on tensor cores via mma.sync.m16n8k8 tf32.

#define D      64
#define BM     128
#define BN     128
#define STRIDE 68              // 64 + 4 pad: (68*g + i) % 32 distinct for g<8,i<4
#define SMEM_BYTES (2 * BM * STRIDE * 4)
#define MAXNQ  16384

__device__ float g_s_sq[MAXNQ];
__device__ float g_t_sq[MAXNQ];

__global__ void norms_kernel(const float* __restrict__ s,
                             const float* __restrict__ t,
                             int n, int q) {
    int i = blockIdx.x * blockDim.x + threadIdx.x;
    const float* src = (blockIdx.y == 0) ? s : t;
    float* dst = (blockIdx.y == 0) ? g_s_sq : g_t_sq;
    int lim = (blockIdx.y == 0) ? n : q;
    if (i < lim) {
        const float4* row = reinterpret_cast<const float4*>(src + (size_t)i * D);
        float acc = 0.f;
#pragma unroll
        for (int j = 0; j < D / 4; j++) {
            float4 v = row[j];
            acc += v.x * v.x + v.y * v.y + v.z * v.z + v.w * v.w;
        }
        dst[i] = acc;
    }
}

__device__ __forceinline__ uint32_t f2tf32(float x) {
    uint32_t r;
    asm("cvt.rna.tf32.f32 %0, %1;" : "=r"(r) : "f"(x));
    return r;
}

__device__ __forceinline__ void mma_tf32(float c[4], const uint32_t a[4],
                                         const uint32_t b[2]) {
    asm volatile(
        "mma.sync.aligned.m16n8k8.row.col.f32.tf32.tf32.f32 "
        "{%0,%1,%2,%3}, {%4,%5,%6,%7}, {%8,%9}, {%0,%1,%2,%3};"
        : "+f"(c[0]), "+f"(c[1]), "+f"(c[2]), "+f"(c[3])
        : "r"(a[0]), "r"(a[1]), "r"(a[2]), "r"(a[3]), "r"(b[0]), "r"(b[1]));
}

// 128x128 tile per CTA, 256 threads = 8 warps in 2x4; each warp 64x32.
__global__ __launch_bounds__(256, 2)
void dist_tc_kernel(const float* __restrict__ s,
                    const float* __restrict__ t,
                    float* __restrict__ out,
                    int n, int q) {
    extern __shared__ float smem[];
    float* sS = smem;                 // [BM][STRIDE]
    float* sT = smem + BM * STRIDE;   // [BN][STRIDE]

    const int tid  = threadIdx.x;
    const int lane = tid & 31;
    const int warp = tid >> 5;
    const int wm   = warp >> 2;       // 0..1
    const int wn   = warp & 3;        // 0..3
    const int g    = lane >> 2;       // 0..7
    const int i4   = lane & 3;        // 0..3

    const int rowBase = blockIdx.y * BM;
    const int colBase = blockIdx.x * BN;

    // ---- Stage both tiles (K=64 entirely) with tf32 rounding ----
    // 128 rows x 16 float4 = 2048 float4 per tile; 256 threads x 8 iters.
#pragma unroll
    for (int it = 0; it < 8; it++) {
        const int idx = tid + it * 256;
        const int row = idx >> 4;
        const int c4  = (idx & 15) << 2;
        float4 v = *reinterpret_cast<const float4*>(
            s + (size_t)(rowBase + row) * D + c4);
        uint4 u;
        u.x = f2tf32(v.x); u.y = f2tf32(v.y); u.z = f2tf32(v.z); u.w = f2tf32(v.w);
        *reinterpret_cast<uint4*>(sS + row * STRIDE + c4) = u;
        float4 w = *reinterpret_cast<const float4*>(
            t + (size_t)(colBase + row) * D + c4);
        uint4 x;
        x.x = f2tf32(w.x); x.y = f2tf32(w.y); x.z = f2tf32(w.z); x.w = f2tf32(w.w);
        *reinterpret_cast<uint4*>(sT + row * STRIDE + c4) = x;
    }
    __syncthreads();

    float acc[4][4][4];
#pragma unroll
    for (int a = 0; a < 4; a++)
#pragma unroll
        for (int b = 0; b < 4; b++)
#pragma unroll
            for (int c = 0; c < 4; c++) acc[a][b][c] = 0.f;

    const int mrow = wm * 64;
    const int ncol = wn * 32;

    // ---- Mainloop: 8 k-steps of 8 ----
#pragma unroll
    for (int kk = 0; kk < 8; kk++) {
        const int k = kk * 8;
        uint32_t a[4][4];
#pragma unroll
        for (int mf = 0; mf < 4; mf++) {
            const float* base = sS + (size_t)(mrow + mf * 16 + g) * STRIDE + k + i4;
            a[mf][0] = __float_as_uint(base[0]);
            a[mf][1] = __float_as_uint(base[8 * STRIDE]);
            a[mf][2] = __float_as_uint(base[4]);
            a[mf][3] = __float_as_uint(base[8 * STRIDE + 4]);
        }
        uint32_t b[4][2];
#pragma unroll
        for (int nf = 0; nf < 4; nf++) {
            const float* base = sT + (size_t)(ncol + nf * 8 + g) * STRIDE + k + i4;
            b[nf][0] = __float_as_uint(base[0]);
            b[nf][1] = __float_as_uint(base[4]);
        }
#pragma unroll
        for (int mf = 0; mf < 4; mf++)
#pragma unroll
            for (int nf = 0; nf < 4; nf++)
                mma_tf32(acc[mf][nf], a[mf], b[nf]);
    }

    // ---- Epilogue: dist = ssq + tsq - 2*cross, float2 stores ----
#pragma unroll
    for (int mf = 0; mf < 4; mf++) {
        const int r0 = rowBase + mrow + mf * 16 + g;
        const float s0 = g_s_sq[r0];
        const float s1 = g_s_sq[r0 + 8];
#pragma unroll
        for (int nf = 0; nf < 4; nf++) {
            const int c = colBase + ncol + nf * 8 + 2 * i4;
            const float t0 = g_t_sq[c];
            const float t1 = g_t_sq[c + 1];
            float2 v0, v1;
            v0.x = s0 + t0 - 2.f * acc[mf][nf][0];
            v0.y = s0 + t1 - 2.f * acc[mf][nf][1];
            v1.x = s1 + t0 - 2.f * acc[mf][nf][2];
            v1.y = s1 + t1 - 2.f * acc[mf][nf][3];
            *reinterpret_cast<float2*>(out + (size_t)r0 * q + c) = v0;
            *reinterpret_cast<float2*>(out + (size_t)(r0 + 8) * q + c) = v1;
        }
    }
}

extern "C" void kernel_launch(void* const* d_in, const int* in_sizes, int n_in,
                              void* d_out, int out_size) {
    const float* s = (const float*)d_in[0];
    const float* t = (const float*)d_in[1];
    float* out = (float*)d_out;

    const int n = in_sizes[0] / D;
    const int q = in_sizes[1] / D;

    cudaFuncSetAttribute(dist_tc_kernel,
                         cudaFuncAttributeMaxDynamicSharedMemorySize, SMEM_BYTES);

    const int mx = (n > q ? n : q);
    dim3 ngrid((mx + 255) / 256, 2);
    norms_kernel<<<ngrid, 256>>>(s, t, n, q);

    dim3 grid(q / BN, n / BM);
    dist_tc_kernel<<<grid, 256, SMEM_BYTES>>>(s, t, out, n, q);
}

// round 3
// speedup vs baseline: 2.9844x; 1.1801x over previous
#include <cuda_runtime.h>
#include <cuda_bf16.h>
#include <cstdint>

// dist[i,j] = ||s_i||^2 + ||t_j||^2 - 2 <s_i, t_j>
// s: [n, 64] fp32, t: [q, 64] fp32, out: [n, q] fp32. n = q = 16384.
// Cross term: bf16 mma.m16n8k16 with ldmatrix-fed fragments.

#define D    64
#define BM   128
#define BN   256          // per CTA: two 128-wide halves sharing the s tile
#define MAXNQ 16384

__device__ float g_s_sq[MAXNQ];
__device__ float g_t_sq[MAXNQ];

__global__ void norms_kernel(const float* __restrict__ s,
                             const float* __restrict__ t,
                             int n, int q) {
    int i = blockIdx.x * blockDim.x + threadIdx.x;
    const float* src = (blockIdx.y == 0) ? s : t;
    float* dst = (blockIdx.y == 0) ? g_s_sq : g_t_sq;
    int lim = (blockIdx.y == 0) ? n : q;
    if (i < lim) {
        const float4* row = reinterpret_cast<const float4*>(src + (size_t)i * D);
        float acc = 0.f;
#pragma unroll
        for (int j = 0; j < D / 4; j++) {
            float4 v = row[j];
            acc += v.x * v.x + v.y * v.y + v.z * v.z + v.w * v.w;
        }
        dst[i] = acc;
    }
}

__device__ __forceinline__ void ldsm_x4(uint32_t& r0, uint32_t& r1,
                                        uint32_t& r2, uint32_t& r3,
                                        uint32_t addr) {
    asm volatile("ldmatrix.sync.aligned.m8n8.x4.shared.b16 {%0,%1,%2,%3}, [%4];"
                 : "=r"(r0), "=r"(r1), "=r"(r2), "=r"(r3) : "r"(addr));
}

__device__ __forceinline__ void mma_bf16(float c[4], const uint32_t a[4],
                                         uint32_t b0, uint32_t b1) {
    asm volatile(
        "mma.sync.aligned.m16n8k16.row.col.f32.bf16.bf16.f32 "
        "{%0,%1,%2,%3}, {%4,%5,%6,%7}, {%8,%9}, {%0,%1,%2,%3};"
        : "+f"(c[0]), "+f"(c[1]), "+f"(c[2]), "+f"(c[3])
        : "r"(a[0]), "r"(a[1]), "r"(a[2]), "r"(a[3]), "r"(b0), "r"(b1));
}

__device__ __forceinline__ uint32_t pack_bf16x2(float x, float y) {
    __nv_bfloat162 h = __float22bfloat162_rn(make_float2(x, y));
    return *reinterpret_cast<uint32_t*>(&h);
}

// CTA: 128x256 output. 256 threads = 8 warps (2x4); warp tile 64x32 per half.
// Smem: rows of 64 bf16 (128B) with 16B-chunk XOR swizzle: chunk' = chunk ^ (row&7).
__global__ __launch_bounds__(256, 2)
void dist_bf16_kernel(const float* __restrict__ s,
                      const float* __restrict__ t,
                      float* __restrict__ out,
                      int n, int q) {
    __shared__ __nv_bfloat16 sS[BM * D];   // 16 KB
    __shared__ __nv_bfloat16 sT[BN * D];   // 32 KB

    const int tid  = threadIdx.x;
    const int lane = tid & 31;
    const int warp = tid >> 5;
    const int wm   = warp >> 2;      // 0..1
    const int wn   = warp & 3;       // 0..3
    const int g    = lane >> 2;      // 0..7
    const int i4   = lane & 3;       // 0..3

    const int rowBase = blockIdx.y * BM;
    const int colBase = blockIdx.x * BN;

    // ---- Stage: fp32 gmem -> bf16 swizzled smem (16B chunks) ----
    // sS: 128 rows * 8 chunks = 1024; sT: 256 rows * 8 chunks = 2048.
#pragma unroll
    for (int it = 0; it < 4; it++) {
        const int idx = tid + it * 256;
        const int row = idx >> 3, c = idx & 7;
        const float4* p = reinterpret_cast<const float4*>(
            s + (size_t)(rowBase + row) * D + c * 8);
        float4 v0 = p[0], v1 = p[1];
        uint4 u;
        u.x = pack_bf16x2(v0.x, v0.y);
        u.y = pack_bf16x2(v0.z, v0.w);
        u.z = pack_bf16x2(v1.x, v1.y);
        u.w = pack_bf16x2(v1.z, v1.w);
        reinterpret_cast<uint4*>(sS)[row * 8 + (c ^ (row & 7))] = u;
    }
#pragma unroll
    for (int it = 0; it < 8; it++) {
        const int idx = tid + it * 256;
        const int row = idx >> 3, c = idx & 7;
        const float4* p = reinterpret_cast<const float4*>(
            t + (size_t)(colBase + row) * D + c * 8);
        float4 v0 = p[0], v1 = p[1];
        uint4 u;
        u.x = pack_bf16x2(v0.x, v0.y);
        u.y = pack_bf16x2(v0.z, v0.w);
        u.z = pack_bf16x2(v1.x, v1.y);
        u.w = pack_bf16x2(v1.z, v1.w);
        reinterpret_cast<uint4*>(sT)[row * 8 + (c ^ (row & 7))] = u;
    }
    __syncthreads();

    const uint32_t sS_base = (uint32_t)__cvta_generic_to_shared(sS);
    const uint32_t sT_base = (uint32_t)__cvta_generic_to_shared(sT);

    const int mrow = wm * 64;
    // ldmatrix lane addressing (fixed per lane):
    const int aRow  = mrow + (lane & 15);        // + mb*16
    const int aXor  = lane & 7;                  // (row & 7) for A rows
    const int kAdd  = lane >> 4;                 // chunk +0/+1 within k-step
    const int bRowL = (lane & 7) + ((lane >> 3) & 1) * 8;  // + nblk*16 + ncol

#pragma unroll 1
    for (int nb = 0; nb < 2; nb++) {
        const int ncol = nb * 128 + wn * 32;

        float acc[4][4][4];
#pragma unroll
        for (int a = 0; a < 4; a++)
#pragma unroll
            for (int b = 0; b < 4; b++)
#pragma unroll
                for (int c = 0; c < 4; c++) acc[a][b][c] = 0.f;

#pragma unroll
        for (int ks = 0; ks < 4; ks++) {       // K = 4 * 16
            const int k2 = ks * 2;             // base 16B chunk
            uint32_t a[4][4];
#pragma unroll
            for (int mb = 0; mb < 4; mb++) {
                const int row = aRow + mb * 16;
                const uint32_t addr =
                    sS_base + (uint32_t)(row * 8 + ((k2 + kAdd) ^ aXor)) * 16;
                ldsm_x4(a[mb][0], a[mb][1], a[mb][2], a[mb][3], addr);
            }
            uint32_t b[2][4];
#pragma unroll
            for (int nk = 0; nk < 2; nk++) {
                const int trow = ncol + nk * 16 + bRowL;
                const uint32_t addr =
                    sT_base + (uint32_t)(trow * 8 + ((k2 + kAdd) ^ (trow & 7))) * 16;
                ldsm_x4(b[nk][0], b[nk][1], b[nk][2], b[nk][3], addr);
            }
#pragma unroll
            for (int mb = 0; mb < 4; mb++)
#pragma unroll
                for (int nk = 0; nk < 2; nk++) {
                    mma_bf16(acc[mb][nk * 2 + 0], a[mb], b[nk][0], b[nk][2]);
                    mma_bf16(acc[mb][nk * 2 + 1], a[mb], b[nk][1], b[nk][3]);
                }
        }

        // ---- Epilogue for this 128-col half ----
#pragma unroll
        for (int mb = 0; mb < 4; mb++) {
            const int r0 = rowBase + mrow + mb * 16 + g;
            const float s0 = g_s_sq[r0];
            const float s1 = g_s_sq[r0 + 8];
#pragma unroll
            for (int nf = 0; nf < 4; nf++) {
                const int c = colBase + ncol + nf * 8 + 2 * i4;
                const float t0 = g_t_sq[c];
                const float t1 = g_t_sq[c + 1];
                float2 v0, v1;
                v0.x = s0 + t0 - 2.f * acc[mb][nf][0];
                v0.y = s0 + t1 - 2.f * acc[mb][nf][1];
                v1.x = s1 + t0 - 2.f * acc[mb][nf][2];
                v1.y = s1 + t1 - 2.f * acc[mb][nf][3];
                *reinterpret_cast<float2*>(out + (size_t)r0 * q + c) = v0;
                *reinterpret_cast<float2*>(out + (size_t)(r0 + 8) * q + c) = v1;
            }
        }
    }
}

extern "C" void kernel_launch(void* const* d_in, const int* in_sizes, int n_in,
                              void* d_out, int out_size) {
    const float* s = (const float*)d_in[0];
    const float* t = (const float*)d_in[1];
    float* out = (float*)d_out;

    const int n = in_sizes[0] / D;
    const int q = in_sizes[1] / D;

    const int mx = (n > q ? n : q);
    dim3 ngrid((mx + 255) / 256, 2);
    norms_kernel<<<ngrid, 256>>>(s, t, n, q);

    dim3 grid(q / BN, n / BM);
    dist_bf16_kernel<<<grid, 256>>>(s, t, out, n, q);
}

// round 6
// speedup vs baseline: 3.4937x; 1.1707x over previous
#include <cuda_runtime.h>
#include <cuda_bf16.h>
#include <cstdint>

// dist[i,j] = ||s_i||^2 + ||t_j||^2 - 2 <s_i, t_j>
// s: [n, 64] fp32, t: [q, 64] fp32, out: [n, q] fp32. n = q = 16384.
// bf16 mma.m16n8k16 + ldmatrix; shuffle-transposed coalesced epilogue.

#define D    64
#define BM   128
#define BN   256
#define MAXNQ 16384

__device__ float g_s_sq[MAXNQ];
__device__ float g_t_sq[MAXNQ];
__device__ __nv_bfloat16 g_s_bf[MAXNQ * D];
__device__ __nv_bfloat16 g_t_bf[MAXNQ * D];

// ---------------- prep: fp32 -> bf16 copies + row norms ----------------
__global__ void prep_kernel(const float* __restrict__ s,
                            const float* __restrict__ t, int n, int q) {
    const float* src = blockIdx.y ? t : s;
    __nv_bfloat16* dstb = blockIdx.y ? g_t_bf : g_s_bf;
    float* dstn = blockIdx.y ? g_t_sq : g_s_sq;
    const int lim = blockIdx.y ? q : n;
    const int row = blockIdx.x * 64 + (threadIdx.x >> 2);
    const int part = threadIdx.x & 3;
    if (row >= lim) return;
    const float4* p = reinterpret_cast<const float4*>(src + (size_t)row * D) + part * 4;
    float acc = 0.f;
    uint4 u[2];
#pragma unroll
    for (int j = 0; j < 2; j++) {
        float4 a = p[2 * j], b = p[2 * j + 1];
        acc += a.x * a.x + a.y * a.y + a.z * a.z + a.w * a.w;
        acc += b.x * b.x + b.y * b.y + b.z * b.z + b.w * b.w;
        __nv_bfloat162 h0 = __float22bfloat162_rn(make_float2(a.x, a.y));
        __nv_bfloat162 h1 = __float22bfloat162_rn(make_float2(a.z, a.w));
        __nv_bfloat162 h2 = __float22bfloat162_rn(make_float2(b.x, b.y));
        __nv_bfloat162 h3 = __float22bfloat162_rn(make_float2(b.z, b.w));
        u[j].x = *reinterpret_cast<uint32_t*>(&h0);
        u[j].y = *reinterpret_cast<uint32_t*>(&h1);
        u[j].z = *reinterpret_cast<uint32_t*>(&h2);
        u[j].w = *reinterpret_cast<uint32_t*>(&h3);
    }
    acc += __shfl_xor_sync(0xFFFFFFFF, acc, 1);
    acc += __shfl_xor_sync(0xFFFFFFFF, acc, 2);
    uint4* q4 = reinterpret_cast<uint4*>(dstb + (size_t)row * D) + part * 2;
    q4[0] = u[0];
    q4[1] = u[1];
    if (part == 0) dstn[row] = acc;
}

// ---------------- helpers ----------------
__device__ __forceinline__ void ldsm_x4(uint32_t& r0, uint32_t& r1,
                                        uint32_t& r2, uint32_t& r3,
                                        uint32_t addr) {
    asm volatile("ldmatrix.sync.aligned.m8n8.x4.shared.b16 {%0,%1,%2,%3}, [%4];"
                 : "=r"(r0), "=r"(r1), "=r"(r2), "=r"(r3) : "r"(addr));
}

__device__ __forceinline__ void mma_bf16(float c[4], const uint32_t a[4],
                                         uint32_t b0, uint32_t b1) {
    asm volatile(
        "mma.sync.aligned.m16n8k16.row.col.f32.bf16.bf16.f32 "
        "{%0,%1,%2,%3}, {%4,%5,%6,%7}, {%8,%9}, {%0,%1,%2,%3};"
        : "+f"(c[0]), "+f"(c[1]), "+f"(c[2]), "+f"(c[3])
        : "r"(a[0]), "r"(a[1]), "r"(a[2]), "r"(a[3]), "r"(b0), "r"(b1));
}

__device__ __forceinline__ float2 shfl_xor_f2(float2 v, int m) {
    float2 r;
    r.x = __shfl_xor_sync(0xFFFFFFFFu, v.x, m);
    r.y = __shfl_xor_sync(0xFFFFFFFFu, v.y, m);
    return r;
}

// CTA: 128x256 output. 256 threads = 8 warps (2x4); warp tile 64x32 per half.
// Smem: rows of 64 bf16 (128B) with 16B-chunk XOR swizzle: chunk' = chunk ^ (row&7).
__global__ __launch_bounds__(256, 2)
void dist_bf16_kernel(float* __restrict__ out, int q) {
    __shared__ __nv_bfloat16 sS[BM * D];   // 16 KB
    __shared__ __nv_bfloat16 sT[BN * D];   // 32 KB
    __shared__ float sSn[BM];
    __shared__ float sTn[BN];

    const int tid  = threadIdx.x;
    const int lane = tid & 31;
    const int warp = tid >> 5;
    const int wm   = warp >> 2;      // 0..1
    const int wn   = warp & 3;       // 0..3
    const int g    = lane >> 2;      // 0..7
    const int i4   = lane & 3;       // 0..3

    const int rowBase = blockIdx.y * BM;
    const int colBase = blockIdx.x * BN;

    // ---- Stage bf16 tiles + norms ----
#pragma unroll
    for (int it = 0; it < 4; it++) {
        const int idx = tid + it * 256;
        const int row = idx >> 3, c = idx & 7;
        uint4 v = reinterpret_cast<const uint4*>(
            g_s_bf + ((size_t)(rowBase + row) << 6))[c];
        reinterpret_cast<uint4*>(sS)[row * 8 + (c ^ (row & 7))] = v;
    }
#pragma unroll
    for (int it = 0; it < 8; it++) {
        const int idx = tid + it * 256;
        const int row = idx >> 3, c = idx & 7;
        uint4 v = reinterpret_cast<const uint4*>(
            g_t_bf + ((size_t)(colBase + row) << 6))[c];
        reinterpret_cast<uint4*>(sT)[row * 8 + (c ^ (row & 7))] = v;
    }
    if (tid < BM) sSn[tid] = g_s_sq[rowBase + tid];
    sTn[tid] = g_t_sq[colBase + tid];
    __syncthreads();

    const uint32_t sS_base = (uint32_t)__cvta_generic_to_shared(sS);
    const uint32_t sT_base = (uint32_t)__cvta_generic_to_shared(sT);

    const int mrow = wm * 64;
    const int aRow  = mrow + (lane & 15);                 // + mb*16
    const int aXor  = lane & 7;
    const int kAdd  = lane >> 4;                          // chunk +0/+1
    const int bRowL = (lane & 7) + ((lane >> 3) & 1) * 8; // + nk*16 + ncol

#pragma unroll 1
    for (int nb = 0; nb < 2; nb++) {
        const int ncol = nb * 128 + wn * 32;

        float acc[4][4][4];
#pragma unroll
        for (int a = 0; a < 4; a++)
#pragma unroll
            for (int b = 0; b < 4; b++)
#pragma unroll
                for (int c = 0; c < 4; c++) acc[a][b][c] = 0.f;

#pragma unroll
        for (int ks = 0; ks < 4; ks++) {       // K = 4 * 16
            const int k2 = ks * 2;
            uint32_t a[4][4];
#pragma unroll
            for (int mb = 0; mb < 4; mb++) {
                const int row = aRow + mb * 16;
                const uint32_t addr =
                    sS_base + (uint32_t)(row * 8 + ((k2 + kAdd) ^ aXor)) * 16;
                ldsm_x4(a[mb][0], a[mb][1], a[mb][2], a[mb][3], addr);
            }
            uint32_t b[2][4];
#pragma unroll
            for (int nk = 0; nk < 2; nk++) {
                const int trow = ncol + nk * 16 + bRowL;
                const uint32_t addr =
                    sT_base + (uint32_t)(trow * 8 + ((k2 + kAdd) ^ (trow & 7))) * 16;
                ldsm_x4(b[nk][0], b[nk][1], b[nk][2], b[nk][3], addr);
            }
#pragma unroll
            for (int mb = 0; mb < 4; mb++)
#pragma unroll
                for (int nk = 0; nk < 2; nk++) {
                    mma_bf16(acc[mb][nk * 2 + 0], a[mb], b[nk][0], b[nk][2]);
                    mma_bf16(acc[mb][nk * 2 + 1], a[mb], b[nk][1], b[nk][3]);
                }
        }

        // ---- Epilogue: quad transpose -> coalesced STG.128 ----
        // Per lane (pre-transpose): p[nf] = cols (8nf+2*i4, +1) of row r.
        // After 2-stage butterfly: p[k] = cols (8*i4+2k, +1) of row r.
        const float4 tn0 = *reinterpret_cast<const float4*>(&sTn[ncol + 8 * i4]);
        const float4 tn1 = *reinterpret_cast<const float4*>(&sTn[ncol + 8 * i4 + 4]);

#pragma unroll
        for (int mb = 0; mb < 4; mb++) {
#pragma unroll
            for (int h = 0; h < 2; h++) {
                float2 pv[4];
#pragma unroll
                for (int nf = 0; nf < 4; nf++)
                    pv[nf] = make_float2(acc[mb][nf][2 * h], acc[mb][nf][2 * h + 1]);

                // stage b=1: p[k] = ((i4^k)&1) ? shfl_xor(p[k^1],1) : p[k]
                {
                    float2 t0 = shfl_xor_f2(pv[1], 1);
                    float2 t1 = shfl_xor_f2(pv[0], 1);
                    float2 t2 = shfl_xor_f2(pv[3], 1);
                    float2 t3 = shfl_xor_f2(pv[2], 1);
                    if (i4 & 1) { pv[0] = t0; pv[2] = t2; }
                    else        { pv[1] = t1; pv[3] = t3; }
                }
                // stage b=2: p[k] = ((i4^k)&2) ? shfl_xor(p[k^2],2) : p[k]
                {
                    float2 u0 = shfl_xor_f2(pv[2], 2);
                    float2 u1 = shfl_xor_f2(pv[3], 2);
                    float2 u2 = shfl_xor_f2(pv[0], 2);
                    float2 u3 = shfl_xor_f2(pv[1], 2);
                    if (i4 & 2) { pv[0] = u0; pv[1] = u1; }
                    else        { pv[2] = u2; pv[3] = u3; }
                }

                const int r = mrow + mb * 16 + g + 8 * h;
                const float srow = sSn[r];
                float4 o0, o1;
                o0.x = fmaf(-2.f, pv[0].x, srow + tn0.x);
                o0.y = fmaf(-2.f, pv[0].y, srow + tn0.y);
                o0.z = fmaf(-2.f, pv[1].x, srow + tn0.z);
                o0.w = fmaf(-2.f, pv[1].y, srow + tn0.w);
                o1.x = fmaf(-2.f, pv[2].x, srow + tn1.x);
                o1.y = fmaf(-2.f, pv[2].y, srow + tn1.y);
                o1.z = fmaf(-2.f, pv[3].x, srow + tn1.z);
                o1.w = fmaf(-2.f, pv[3].y, srow + tn1.w);

                float* dst = out + (size_t)(rowBase + r) * q + colBase + ncol + 8 * i4;
                *reinterpret_cast<float4*>(dst)     = o0;
                *reinterpret_cast<float4*>(dst + 4) = o1;
            }
        }
    }
}

extern "C" void kernel_launch(void* const* d_in, const int* in_sizes, int n_in,
                              void* d_out, int out_size) {
    const float* s = (const float*)d_in[0];
    const float* t = (const float*)d_in[1];
    float* out = (float*)d_out;

    const int n = in_sizes[0] / D;
    const int q = in_sizes[1] / D;

    dim3 pgrid((((n > q) ? n : q) + 63) / 64, 2);
    prep_kernel<<<pgrid, 256>>>(s, t, n, q);

    dim3 grid(q / BN, n / BM);
    dist_bf16_kernel<<<grid, 256>>>(out, q);
}

// round 7
// speedup vs baseline: 4.0814x; 1.1682x over previous
#include <cuda_runtime.h>
#include <cuda_bf16.h>
#include <cstdint>

// dist[i,j] = ||s_i||^2 + ||t_j||^2 - 2 <s_i, t_j>
// s: [n, 64] fp32, t: [q, 64] fp32, out: [n, q] fp32. n = q = 16384.
// bf16 mma.m16n8k16 + ldmatrix; tiles pre-swizzled in gmem and DMA'd to smem
// via cp.async.bulk; shuffle-transposed coalesced epilogue.

#define D    64
#define BM   128
#define BN   256
#define MAXNQ 16384

__device__ float g_s_sq[MAXNQ];
__device__ float g_t_sq[MAXNQ];
// Pre-swizzled bf16 tiles: within each 128B row, 16B chunk c stored at c^(row&7).
__device__ __nv_bfloat16 g_s_bf[MAXNQ * D];
__device__ __nv_bfloat16 g_t_bf[MAXNQ * D];

// ---------------- prep: fp32 -> pre-swizzled bf16 + row norms ----------------
__global__ void prep_kernel(const float* __restrict__ s,
                            const float* __restrict__ t, int n, int q) {
    const float* src = blockIdx.y ? t : s;
    __nv_bfloat16* dstb = blockIdx.y ? g_t_bf : g_s_bf;
    float* dstn = blockIdx.y ? g_t_sq : g_s_sq;
    const int lim = blockIdx.y ? q : n;
    const int row = blockIdx.x * 64 + (threadIdx.x >> 2);
    const int part = threadIdx.x & 3;
    if (row >= lim) return;
    const float4* p = reinterpret_cast<const float4*>(src + (size_t)row * D) + part * 4;
    float acc = 0.f;
    uint4* rowq = reinterpret_cast<uint4*>(dstb + (size_t)row * D);
    const int sw = row & 7;
#pragma unroll
    for (int j = 0; j < 2; j++) {
        float4 a = p[2 * j], b = p[2 * j + 1];
        acc += a.x * a.x + a.y * a.y + a.z * a.z + a.w * a.w;
        acc += b.x * b.x + b.y * b.y + b.z * b.z + b.w * b.w;
        __nv_bfloat162 h0 = __float22bfloat162_rn(make_float2(a.x, a.y));
        __nv_bfloat162 h1 = __float22bfloat162_rn(make_float2(a.z, a.w));
        __nv_bfloat162 h2 = __float22bfloat162_rn(make_float2(b.x, b.y));
        __nv_bfloat162 h3 = __float22bfloat162_rn(make_float2(b.z, b.w));
        uint4 u;
        u.x = *reinterpret_cast<uint32_t*>(&h0);
        u.y = *reinterpret_cast<uint32_t*>(&h1);
        u.z = *reinterpret_cast<uint32_t*>(&h2);
        u.w = *reinterpret_cast<uint32_t*>(&h3);
        rowq[(part * 2 + j) ^ sw] = u;   // pre-apply ldmatrix swizzle
    }
    acc += __shfl_xor_sync(0xFFFFFFFF, acc, 1);
    acc += __shfl_xor_sync(0xFFFFFFFF, acc, 2);
    if (part == 0) dstn[row] = acc;
}

// ---------------- helpers ----------------
__device__ __forceinline__ void ldsm_x4(uint32_t& r0, uint32_t& r1,
                                        uint32_t& r2, uint32_t& r3,
                                        uint32_t addr) {
    asm volatile("ldmatrix.sync.aligned.m8n8.x4.shared.b16 {%0,%1,%2,%3}, [%4];"
                 : "=r"(r0), "=r"(r1), "=r"(r2), "=r"(r3) : "r"(addr));
}

__device__ __forceinline__ void mma_bf16(float c[4], const uint32_t a[4],
                                         uint32_t b0, uint32_t b1) {
    asm volatile(
        "mma.sync.aligned.m16n8k16.row.col.f32.bf16.bf16.f32 "
        "{%0,%1,%2,%3}, {%4,%5,%6,%7}, {%8,%9}, {%0,%1,%2,%3};"
        : "+f"(c[0]), "+f"(c[1]), "+f"(c[2]), "+f"(c[3])
        : "r"(a[0]), "r"(a[1]), "r"(a[2]), "r"(a[3]), "r"(b0), "r"(b1));
}

__device__ __forceinline__ float2 shfl_xor_f2(float2 v, int m) {
    float2 r;
    r.x = __shfl_xor_sync(0xFFFFFFFFu, v.x, m);
    r.y = __shfl_xor_sync(0xFFFFFFFFu, v.y, m);
    return r;
}

__device__ __forceinline__ void bulk_cp(uint32_t dst, const void* src,
                                        uint32_t bytes, uint32_t mbar) {
    asm volatile(
        "cp.async.bulk.shared::cluster.global.mbarrier::complete_tx::bytes "
        "[%0], [%1], %2, [%3];"
        :: "r"(dst), "l"(src), "r"(bytes), "r"(mbar) : "memory");
}

// CTA: 128x256 output. 256 threads = 8 warps (2x4); warp tile 64x32 per half.
__global__ __launch_bounds__(256, 2)
void dist_bf16_kernel(float* __restrict__ out, int q) {
    __shared__ __align__(128) __nv_bfloat16 sS[BM * D];   // 16 KB
    __shared__ __align__(128) __nv_bfloat16 sT[BN * D];   // 32 KB
    __shared__ float sSn[BM];
    __shared__ float sTn[BN];
    __shared__ __align__(8) uint64_t mbar;

    const int tid  = threadIdx.x;
    const int lane = tid & 31;
    const int warp = tid >> 5;
    const int wm   = warp >> 2;      // 0..1
    const int wn   = warp & 3;       // 0..3
    const int g    = lane >> 2;      // 0..7
    const int i4   = lane & 3;       // 0..3

    const int rowBase = blockIdx.y * BM;
    const int colBase = blockIdx.x * BN;

    const uint32_t mb = (uint32_t)__cvta_generic_to_shared(&mbar);
    const uint32_t sS_base = (uint32_t)__cvta_generic_to_shared(sS);
    const uint32_t sT_base = (uint32_t)__cvta_generic_to_shared(sT);

    if (tid == 0)
        asm volatile("mbarrier.init.shared.b64 [%0], 1;" :: "r"(mb) : "memory");
    __syncthreads();

    if (tid == 0) {
        asm volatile("mbarrier.arrive.expect_tx.shared.b64 _, [%0], %1;"
                     :: "r"(mb), "r"((uint32_t)(BM * D * 2 + BN * D * 2)) : "memory");
        bulk_cp(sS_base, g_s_bf + ((size_t)rowBase << 6), BM * D * 2, mb);
        bulk_cp(sT_base, g_t_bf + ((size_t)colBase << 6), BN * D * 2, mb);
    }

    // Norms staged by regular loads while DMA runs.
    if (tid < BM) sSn[tid] = g_s_sq[rowBase + tid];
    sTn[tid] = g_t_sq[colBase + tid];

    // Wait for DMA completion (phase 0).
    {
        uint32_t done;
        asm volatile(
            "{\n\t.reg .pred p;\n\t"
            "mbarrier.try_wait.parity.acquire.cta.shared::cta.b64 p, [%1], 0;\n\t"
            "selp.b32 %0, 1, 0, p;\n\t}"
            : "=r"(done) : "r"(mb) : "memory");
        if (!done) {
            asm volatile(
                "{\n\t.reg .pred P1;\n\t"
                "WL_%=:\n\t"
                "mbarrier.try_wait.parity.acquire.cta.shared::cta.b64 P1, [%0], 0, 0x989680;\n\t"
                "@P1 bra.uni WD_%=;\n\tbra.uni WL_%=;\n\tWD_%=:\n\t}"
                :: "r"(mb) : "memory");
        }
    }
    __syncthreads();

    const int mrow = wm * 64;
    const int aRow  = mrow + (lane & 15);                 // + mb*16
    const int aXor  = lane & 7;
    const int kAdd  = lane >> 4;                          // chunk +0/+1
    const int bRowL = (lane & 7) + ((lane >> 3) & 1) * 8; // + nk*16 + ncol

#pragma unroll 1
    for (int nb = 0; nb < 2; nb++) {
        const int ncol = nb * 128 + wn * 32;

        float acc[4][4][4];
#pragma unroll
        for (int a = 0; a < 4; a++)
#pragma unroll
            for (int b = 0; b < 4; b++)
#pragma unroll
                for (int c = 0; c < 4; c++) acc[a][b][c] = 0.f;

#pragma unroll
        for (int ks = 0; ks < 4; ks++) {       // K = 4 * 16
            const int k2 = ks * 2;
            uint32_t a[4][4];
#pragma unroll
            for (int mb2 = 0; mb2 < 4; mb2++) {
                const int row = aRow + mb2 * 16;
                const uint32_t addr =
                    sS_base + (uint32_t)(row * 8 + ((k2 + kAdd) ^ aXor)) * 16;
                ldsm_x4(a[mb2][0], a[mb2][1], a[mb2][2], a[mb2][3], addr);
            }
            uint32_t b[2][4];
#pragma unroll
            for (int nk = 0; nk < 2; nk++) {
                const int trow = ncol + nk * 16 + bRowL;
                const uint32_t addr =
                    sT_base + (uint32_t)(trow * 8 + ((k2 + kAdd) ^ (trow & 7))) * 16;
                ldsm_x4(b[nk][0], b[nk][1], b[nk][2], b[nk][3], addr);
            }
#pragma unroll
            for (int mb2 = 0; mb2 < 4; mb2++)
#pragma unroll
                for (int nk = 0; nk < 2; nk++) {
                    mma_bf16(acc[mb2][nk * 2 + 0], a[mb2], b[nk][0], b[nk][2]);
                    mma_bf16(acc[mb2][nk * 2 + 1], a[mb2], b[nk][1], b[nk][3]);
                }
        }

        // ---- Epilogue: quad transpose -> coalesced STG.128 ----
        const float4 tn0 = *reinterpret_cast<const float4*>(&sTn[ncol + 8 * i4]);
        const float4 tn1 = *reinterpret_cast<const float4*>(&sTn[ncol + 8 * i4 + 4]);

#pragma unroll
        for (int mb2 = 0; mb2 < 4; mb2++) {
#pragma unroll
            for (int h = 0; h < 2; h++) {
                float2 pv[4];
#pragma unroll
                for (int nf = 0; nf < 4; nf++)
                    pv[nf] = make_float2(acc[mb2][nf][2 * h], acc[mb2][nf][2 * h + 1]);

                {
                    float2 t0 = shfl_xor_f2(pv[1], 1);
                    float2 t1 = shfl_xor_f2(pv[0], 1);
                    float2 t2 = shfl_xor_f2(pv[3], 1);
                    float2 t3 = shfl_xor_f2(pv[2], 1);
                    if (i4 & 1) { pv[0] = t0; pv[2] = t2; }
                    else        { pv[1] = t1; pv[3] = t3; }
                }
                {
                    float2 u0 = shfl_xor_f2(pv[2], 2);
                    float2 u1 = shfl_xor_f2(pv[3], 2);
                    float2 u2 = shfl_xor_f2(pv[0], 2);
                    float2 u3 = shfl_xor_f2(pv[1], 2);
                    if (i4 & 2) { pv[0] = u0; pv[1] = u1; }
                    else        { pv[2] = u2; pv[3] = u3; }
                }

                const int r = mrow + mb2 * 16 + g + 8 * h;
                const float srow = sSn[r];
                float4 o0, o1;
                o0.x = fmaf(-2.f, pv[0].x, srow + tn0.x);
                o0.y = fmaf(-2.f, pv[0].y, srow + tn0.y);
                o0.z = fmaf(-2.f, pv[1].x, srow + tn0.z);
                o0.w = fmaf(-2.f, pv[1].y, srow + tn0.w);
                o1.x = fmaf(-2.f, pv[2].x, srow + tn1.x);
                o1.y = fmaf(-2.f, pv[2].y, srow + tn1.y);
                o1.z = fmaf(-2.f, pv[3].x, srow + tn1.z);
                o1.w = fmaf(-2.f, pv[3].y, srow + tn1.w);

                float* dst = out + (size_t)(rowBase + r) * q + colBase + ncol + 8 * i4;
                *reinterpret_cast<float4*>(dst)     = o0;
                *reinterpret_cast<float4*>(dst + 4) = o1;
            }
        }
    }
}

extern "C" void kernel_launch(void* const* d_in, const int* in_sizes, int n_in,
                              void* d_out, int out_size) {
    const float* s = (const float*)d_in[0];
    const float* t = (const float*)d_in[1];
    float* out = (float*)d_out;

    const int n = in_sizes[0] / D;
    const int q = in_sizes[1] / D;

    dim3 pgrid((((n > q) ? n : q) + 63) / 64, 2);
    prep_kernel<<<pgrid, 256>>>(s, t, n, q);

    dim3 grid(q / BN, n / BM);
    dist_bf16_kernel<<<grid, 256>>>(out, q);
}